// round 11
// baseline (speedup 1.0000x reference)
#include <cuda_runtime.h>
#include <cstdint>
#include <cstring>
#include <cmath>

#define NE 200000
#define NA 20000
#define KC 32
#define USTRIDE 140   // padded per-edge U row (35 float4)

// ---------------------------------------------------------------------------
// Device scratch
// ---------------------------------------------------------------------------
__device__ __align__(16) float g_pool0[NA * 96];
__device__ __align__(16) float g_pool1[NA * 3 * 128];
__device__ __align__(16) float g_pool2[NA * 5 * 128];
__device__ __align__(16) float g_U[(size_t)NE * USTRIDE];

// CSR over centers
__device__ int g_count[NA];
__device__ int g_off[NA];
__device__ int g_cursor[NA];
__device__ int g_eid[NE];

// CG + metadata passed by value (3020 B < 4KB param limit)
struct UParam { float cg[615]; int md[140]; };

// ---------------------------------------------------------------------------
// Host-side bit-exact replication of np.random.default_rng(42).normal(...)
// ---------------------------------------------------------------------------
namespace cgen {

typedef unsigned __int128 u128;

struct Pcg64 {
    u128 state, inc;
    uint64_t next() {
        const u128 MUL = (((u128)0x2360ed051fc65da4ULL) << 64) | 0x4385df649fccf645ULL;
        state = state * MUL + inc;
        uint64_t hi = (uint64_t)(state >> 64);
        uint64_t lo = (uint64_t)state;
        uint64_t v  = hi ^ lo;
        unsigned rot = (unsigned)(state >> 122);
        return (v >> rot) | (v << ((64u - rot) & 63u));
    }
    double nextd() { return (double)(next() >> 11) * (1.0 / 9007199254740992.0); }
};

static float   h_cg[615];
static UParam  h_up;

struct Init {
    uint64_t zki[256];
    double   zwi[256], zfi[256];
    Pcg64    g;

    double znorm() {
        const double NOR_R = 3.6541528853610088;
        const double NOR_INV_R = 0.27366123732975828;
        for (;;) {
            uint64_t r = g.next();
            int idx = (int)(r & 0xff);
            r >>= 8;
            int sign = (int)(r & 1);
            uint64_t rabs = (r >> 1) & 0x000fffffffffffffULL;
            double x = (double)rabs * zwi[idx];
            if (sign) x = -x;
            if (rabs < zki[idx]) return x;
            if (idx == 0) {
                double xx, yy;
                do {
                    xx = -NOR_INV_R * std::log1p(-g.nextd());
                    yy = -std::log1p(-g.nextd());
                } while (yy + yy <= xx * xx);
                return ((rabs >> 8) & 1) ? -(NOR_R + xx) : NOR_R + xx;
            } else {
                if ((zfi[idx - 1] - zfi[idx]) * g.nextd() + zfi[idx] <
                    std::exp(-0.5 * x * x))
                    return x;
            }
        }
    }

    Init() {
        // ---- SeedSequence(42), pool_size=4 ----
        uint32_t pool[4];
        uint32_t hc = 0x43b0d7e5u;
        auto hashmix = [&hc](uint32_t v) -> uint32_t {
            v ^= hc; hc *= 0x931e8875u; v *= hc; v ^= v >> 16; return v;
        };
        auto mix = [](uint32_t x, uint32_t y) -> uint32_t {
            uint32_t r = x * 0xca01f9ddu - y * 0x4973f715u; r ^= r >> 16; return r;
        };
        pool[0] = hashmix(42u);
        pool[1] = hashmix(0u);
        pool[2] = hashmix(0u);
        pool[3] = hashmix(0u);
        for (int s = 0; s < 4; s++)
            for (int d = 0; d < 4; d++)
                if (s != d) pool[d] = mix(pool[d], hashmix(pool[s]));

        // ---- generate_state(4, uint64) ----
        uint32_t hc2 = 0x8b51f9ddu;
        uint32_t st32[8];
        for (int i = 0; i < 8; i++) {
            uint32_t v = pool[i & 3];
            v ^= hc2; hc2 *= 0x58f38dedu; v *= hc2; v ^= v >> 16;
            st32[i] = v;
        }
        uint64_t s64[4];
        for (int i = 0; i < 4; i++)
            s64[i] = (uint64_t)st32[2 * i] | ((uint64_t)st32[2 * i + 1] << 32);

        // ---- PCG64 seeding ----
        u128 initstate = (((u128)s64[0]) << 64) | s64[1];
        u128 initseq   = (((u128)s64[2]) << 64) | s64[3];
        const u128 MUL = (((u128)0x2360ed051fc65da4ULL) << 64) | 0x4385df649fccf645ULL;
        g.inc = (initseq << 1) | 1;
        g.state = 0;
        g.state = g.state * MUL + g.inc;
        g.state += initstate;
        g.state = g.state * MUL + g.inc;

        // ---- ziggurat tables ----
        const double r = 3.6541528853610088;
        const double M52 = 4503599627370496.0;
        double f_r = std::exp(-0.5 * r * r);
        double V = r * f_r + 1.2533141373155003 * std::erfc(r * 0.7071067811865476);
        double q = V / f_r;
        zki[0] = (uint64_t)((r / q) * M52);
        zki[1] = 0;
        zwi[0] = q / M52; zwi[255] = r / M52;
        zfi[0] = 1.0;     zfi[255] = f_r;
        double dn = r, tn = r;
        for (int i = 254; i >= 1; i--) {
            dn = std::sqrt(-2.0 * std::log(V / dn + std::exp(-0.5 * dn * dn)));
            zki[i + 1] = (uint64_t)((dn / tn) * M52);
            tn = dn;
            zfi[i] = std::exp(-0.5 * dn * dn);
            zwi[i] = dn / M52;
        }

        // ---- draw all 15 CG tensors in dict order ----
        int pos = 0;
        for (int l1 = 0; l1 <= 2; l1++)
            for (int l2 = 0; l2 <= 2; l2++) {
                int lo = l1 > l2 ? l1 - l2 : l2 - l1;
                int hi = (l1 + l2 < 2) ? (l1 + l2) : 2;
                for (int L = lo; L <= hi; L++) {
                    int n = (2 * l1 + 1) * (2 * l2 + 1) * (2 * L + 1);
                    for (int i = 0; i < n; i++)
                        h_cg[pos++] = (float)(znorm() * 0.3);
                }
            }
        std::memcpy(h_up.cg, h_cg, sizeof(h_cg));

        // ---- U metadata table: 11 even-parity paths, padded layout ----
        // md[u] = sh_base | (n_a<<4) | (a_stride<<8) | (cg0<<16)
        struct PathH { int l1, l2, L, base, uoff; };
        const PathH P[11] = {
            {0,0,0,  0,  0},{1,1,0, 44,  4},{2,2,0,390,  8},
            {0,1,1,  1, 16},{1,0,1, 35, 28},{1,2,1,125, 32},{2,1,1,270, 48},
            {0,2,2, 10, 60},{1,1,2, 80, 88},{2,0,2,245,104},{2,2,2,490,112}};
        std::memset(h_up.md, 0, sizeof(h_up.md));
        for (int p = 0; p < 11; p++) {
            int dimL = 2 * P[p].L + 1, dim2 = 2 * P[p].l2 + 1;
            int n_a = 2 * P[p].l1 + 1;
            int ast = dim2 * dimL;
            int shb = (P[p].l1 == 0) ? 0 : (P[p].l1 == 1 ? 1 : 4);
            for (int b = 0; b < dim2; b++)
                for (int M = 0; M < dimL; M++) {
                    int u   = P[p].uoff + b * dimL + M;
                    int cg0 = P[p].base + b * dimL + M;
                    h_up.md[u] = shb | (n_a << 4) | (ast << 8) | (cg0 << 16);
                }
        }
    }
};
static Init g_init;

} // namespace cgen

// ---------------------------------------------------------------------------
// CSR build kernels
// ---------------------------------------------------------------------------
__global__ void zero_counts_kernel() {
    int i = blockIdx.x * blockDim.x + threadIdx.x;
    if (i < NA) g_count[i] = 0;
}

__global__ void hist_kernel(const int* __restrict__ centers) {
    int e = blockIdx.x * blockDim.x + threadIdx.x;
    if (e < NE) atomicAdd(&g_count[centers[e]], 1);
}

__global__ void scan_kernel() {
    __shared__ int s[1024];
    const int t = threadIdx.x;
    const int CH = 20;
    int base = t * CH;
    int loc[CH];
    int sum = 0;
#pragma unroll
    for (int i = 0; i < CH; i++) {
        int idx = base + i;
        int c = (idx < NA) ? g_count[idx] : 0;
        loc[i] = sum;
        sum += c;
    }
    s[t] = sum;
    __syncthreads();
    for (int d = 1; d < 1024; d <<= 1) {
        int v = (t >= d) ? s[t - d] : 0;
        __syncthreads();
        s[t] += v;
        __syncthreads();
    }
    int excl = (t == 0) ? 0 : s[t - 1];
#pragma unroll
    for (int i = 0; i < CH; i++) {
        int idx = base + i;
        if (idx < NA) {
            int o = excl + loc[i];
            g_off[idx] = o;
            g_cursor[idx] = o;
        }
    }
}

__global__ void scatter_kernel(const int* __restrict__ centers) {
    int e = blockIdx.x * blockDim.x + threadIdx.x;
    if (e < NE) {
        int p = atomicAdd(&g_cursor[centers[e]], 1);
        g_eid[p] = e;
    }
}

// ---------------------------------------------------------------------------
// Kernel A: per-edge U precompute. warp = edge, lanes split the 140 U slots.
// U[e, b, M] = sum_a sh_l1[e,a] * CG[a,b,M]   (lane-uniform values)
// ---------------------------------------------------------------------------
__global__ void __launch_bounds__(256) uexp_kernel(
    UParam up,
    const float* __restrict__ sh0, const float* __restrict__ sh1,
    const float* __restrict__ sh2)
{
    __shared__ float scg[615];
    __shared__ int   smd[140];
    __shared__ float ssh[8][12];
    for (int i = threadIdx.x; i < 615; i += 256) scg[i] = up.cg[i];
    for (int i = threadIdx.x; i < 140; i += 256) smd[i] = up.md[i];
    __syncthreads();

    const int wid  = threadIdx.x >> 5;
    const int lane = threadIdx.x & 31;
    const int e = blockIdx.x * 8 + wid;
    if (e >= NE) return;

    if (lane == 0)      ssh[wid][0]    = __ldg(sh0 + e);
    else if (lane < 4)  ssh[wid][lane] = __ldg(sh1 + 3 * e + lane - 1);
    else if (lane < 9)  ssh[wid][lane] = __ldg(sh2 + 5 * e + lane - 4);
    __syncwarp();

    float* out = g_U + (size_t)e * USTRIDE;
    for (int u = lane; u < USTRIDE; u += 32) {
        int m = smd[u];
        int shb = m & 15, na = (m >> 4) & 15, ast = (m >> 8) & 255, cg = m >> 16;
        float acc = 0.f;
        for (int a = 0; a < na; a++)
            acc = fmaf(ssh[wid][shb + a], scg[cg + a * ast], acc);
        out[u] = acc;
    }
}

// ---------------------------------------------------------------------------
// Kernel B: per-atom gather using U. warp = atom, lane = channel k.
// ---------------------------------------------------------------------------
template <int N4>
__device__ __forceinline__ void loadU(float* d, const float* s) {
#pragma unroll
    for (int j = 0; j < N4; j++) {
        float4 v = __ldg(reinterpret_cast<const float4*>(s) + j);
        d[4 * j + 0] = v.x; d[4 * j + 1] = v.y;
        d[4 * j + 2] = v.z; d[4 * j + 3] = v.w;
    }
}

__global__ void __launch_bounds__(256) gather_kernel(
    const float* __restrict__ radial,
    const float* __restrict__ feat0, const float* __restrict__ feat1,
    const float* __restrict__ feat2,
    const int* __restrict__ neighbors)
{
    const int k = threadIdx.x & 31;
    const int atom = blockIdx.x * 8 + (threadIdx.x >> 5);
    if (atom >= NA) return;

    const int beg = g_off[atom];
    const int end = beg + g_count[atom];

    float A[3] = {0.f, 0.f, 0.f};
    float B[12], C[20];
#pragma unroll
    for (int i = 0; i < 12; i++) B[i] = 0.f;
#pragma unroll
    for (int i = 0; i < 20; i++) C[i] = 0.f;

    int e  = (beg < end) ? __ldg(g_eid + beg) : 0;
    int nb = (beg < end) ? __ldg(neighbors + e) : 0;

    for (int it = beg; it < end; it++) {
        // software-pipeline the index chain one iteration ahead
        int e_n = e, nb_n = nb;
        if (it + 1 < end) {
            e_n  = __ldg(g_eid + it + 1);
            nb_n = __ldg(neighbors + e_n);
        }

        const float* Ue = g_U + (size_t)e * USTRIDE;
        const float r0 = radial[(size_t)e * KC + k];
        const float r1 = radial[(size_t)NE * KC + (size_t)e * KC + k];
        const float r2 = radial[2 * (size_t)NE * KC + (size_t)e * KC + k];

        const float f0 = feat0[(size_t)nb * KC + k];
        float f1[3], f2[5];
#pragma unroll
        for (int a = 0; a < 3; a++) f1[a] = feat1[((size_t)nb * 3 + a) * KC + k];
#pragma unroll
        for (int a = 0; a < 5; a++) f2[a] = feat2[((size_t)nb * 5 + a) * KC + k];

        // ---- P0 (0,0,0) @0 (1) + P1 (1,1,0) @4 (3) ----
        {
            float u[8]; loadU<2>(u, Ue + 0);
            A[0] = fmaf(r0 * f0, u[0], A[0]);
            A[1] = fmaf(r1, f1[0] * u[4] + f1[1] * u[5] + f1[2] * u[6], A[1]);
        }
        // ---- P2 (2,2,0) @8 (5) ----
        {
            float u[8]; loadU<2>(u, Ue + 8);
            float s = f2[0]*u[0] + f2[1]*u[1] + f2[2]*u[2] + f2[3]*u[3] + f2[4]*u[4];
            A[2] = fmaf(r2, s, A[2]);
        }
        // ---- P3 (0,1,1) @16 (9): B[M] += r0 * sum_b f1[b]*u[b*3+M] ----
        {
            float u[12]; loadU<3>(u, Ue + 16);
#pragma unroll
            for (int M = 0; M < 3; M++) {
                float s = 0.f;
#pragma unroll
                for (int b = 0; b < 3; b++) s = fmaf(f1[b], u[b * 3 + M], s);
                B[M] = fmaf(r0, s, B[M]);
            }
        }
        // ---- P4 (1,0,1) @28 (3): B[3+M] += r1 * f0*u[M] ----
        {
            float u[4]; loadU<1>(u, Ue + 28);
#pragma unroll
            for (int M = 0; M < 3; M++) B[3 + M] = fmaf(r1, f0 * u[M], B[3 + M]);
        }
        // ---- P5 (1,2,1) @32 (15): B[6+M] += r1 * sum_b f2[b]*u[b*3+M] ----
        {
            float u[16]; loadU<4>(u, Ue + 32);
#pragma unroll
            for (int M = 0; M < 3; M++) {
                float s = 0.f;
#pragma unroll
                for (int b = 0; b < 5; b++) s = fmaf(f2[b], u[b * 3 + M], s);
                B[6 + M] = fmaf(r1, s, B[6 + M]);
            }
        }
        // ---- P6 (2,1,1) @48 (9): B[9+M] += r2 * sum_b f1[b]*u[b*3+M] ----
        {
            float u[12]; loadU<3>(u, Ue + 48);
#pragma unroll
            for (int M = 0; M < 3; M++) {
                float s = 0.f;
#pragma unroll
                for (int b = 0; b < 3; b++) s = fmaf(f1[b], u[b * 3 + M], s);
                B[9 + M] = fmaf(r2, s, B[9 + M]);
            }
        }
        // ---- P7 (0,2,2) @60 (25): C[M] += r0 * sum_b f2[b]*u[b*5+M] ----
        {
            float u[28]; loadU<7>(u, Ue + 60);
#pragma unroll
            for (int M = 0; M < 5; M++) {
                float s = 0.f;
#pragma unroll
                for (int b = 0; b < 5; b++) s = fmaf(f2[b], u[b * 5 + M], s);
                C[M] = fmaf(r0, s, C[M]);
            }
        }
        // ---- P8 (1,1,2) @88 (15): C[5+M] += r1 * sum_b f1[b]*u[b*5+M] ----
        {
            float u[16]; loadU<4>(u, Ue + 88);
#pragma unroll
            for (int M = 0; M < 5; M++) {
                float s = 0.f;
#pragma unroll
                for (int b = 0; b < 3; b++) s = fmaf(f1[b], u[b * 5 + M], s);
                C[5 + M] = fmaf(r1, s, C[5 + M]);
            }
        }
        // ---- P9 (2,0,2) @104 (5): C[10+M] += r2 * f0*u[M] ----
        {
            float u[8]; loadU<2>(u, Ue + 104);
#pragma unroll
            for (int M = 0; M < 5; M++) C[10 + M] = fmaf(r2, f0 * u[M], C[10 + M]);
        }
        // ---- P10 (2,2,2) @112 (25): C[15+M] += r2 * sum_b f2[b]*u[b*5+M] ----
        {
            float u[28]; loadU<7>(u, Ue + 112);
#pragma unroll
            for (int M = 0; M < 5; M++) {
                float s = 0.f;
#pragma unroll
                for (int b = 0; b < 5; b++) s = fmaf(f2[b], u[b * 5 + M], s);
                C[15 + M] = fmaf(r2, s, C[15 + M]);
            }
        }

        e = e_n; nb = nb_n;
    }

    // ---- write pooled rows (coalesced, no atomics) ----
    float* p0 = g_pool0 + (size_t)atom * 96 + k;
    p0[0]  = A[0];
    p0[32] = A[1];
    p0[64] = A[2];

    float* p1 = g_pool1 + (size_t)atom * 384 + k;
#pragma unroll
    for (int M = 0; M < 3; M++) {
        p1[M * 128 + 0]  = B[0 + M];
        p1[M * 128 + 32] = B[3 + M];
        p1[M * 128 + 64] = B[6 + M];
        p1[M * 128 + 96] = B[9 + M];
    }

    float* p2 = g_pool2 + (size_t)atom * 640 + k;
#pragma unroll
    for (int M = 0; M < 5; M++) {
        p2[M * 128 + 0]  = C[0 + M];
        p2[M * 128 + 32] = C[5 + M];
        p2[M * 128 + 64] = C[10 + M];
        p2[M * 128 + 96] = C[15 + M];
    }
}

// ---------------------------------------------------------------------------
// Kernel C: per-atom linear + bias, *0.1, + residual feat
// ---------------------------------------------------------------------------
__global__ void __launch_bounds__(288) atom_kernel(
    const float* __restrict__ feat0, const float* __restrict__ feat1,
    const float* __restrict__ feat2,
    const float* __restrict__ W0, const float* __restrict__ b0,
    const float* __restrict__ W1, const float* __restrict__ b1,
    const float* __restrict__ W2, const float* __restrict__ b2,
    float* __restrict__ out)
{
    __shared__ __align__(16) float wt0[32 * 100];
    __shared__ __align__(16) float wt1[32 * 132];
    __shared__ __align__(16) float wt2[32 * 132];
    __shared__ float bsh[96];

    for (int i = threadIdx.x; i < 96 * 32; i += 288)
        wt0[(i & 31) * 100 + (i >> 5)] = W0[i];
    for (int i = threadIdx.x; i < 128 * 32; i += 288)
        wt1[(i & 31) * 132 + (i >> 5)] = W1[i];
    for (int i = threadIdx.x; i < 128 * 32; i += 288)
        wt2[(i & 31) * 132 + (i >> 5)] = W2[i];
    if (threadIdx.x < 32) {
        bsh[threadIdx.x]      = b0[threadIdx.x];
        bsh[32 + threadIdx.x] = b1[threadIdx.x];
        bsh[64 + threadIdx.x] = b2[threadIdx.x];
    }
    __syncthreads();

    const int w = threadIdx.x >> 5;
    const int k = threadIdx.x & 31;

    for (int atom = blockIdx.x; atom < NA; atom += gridDim.x) {
        float acc = 0.f;
        if (w == 0) {
            const float4* pr = reinterpret_cast<const float4*>(g_pool0 + (size_t)atom * 96);
            const float4* wr = reinterpret_cast<const float4*>(wt0 + k * 100);
#pragma unroll
            for (int j = 0; j < 24; j++) {
                float4 p = pr[j], wv = wr[j];
                acc += p.x * wv.x + p.y * wv.y + p.z * wv.z + p.w * wv.w;
            }
            int o = atom * 32 + k;
            out[o] = (acc + bsh[k]) * 0.1f + feat0[o];
        } else if (w <= 3) {
            int M = w - 1;
            const float4* pr = reinterpret_cast<const float4*>(g_pool1 + ((size_t)atom * 3 + M) * 128);
            const float4* wr = reinterpret_cast<const float4*>(wt1 + k * 132);
#pragma unroll
            for (int j = 0; j < 32; j++) {
                float4 p = pr[j], wv = wr[j];
                acc += p.x * wv.x + p.y * wv.y + p.z * wv.z + p.w * wv.w;
            }
            int o = (atom * 3 + M) * 32 + k;
            out[NA * 32 + o] = (acc + bsh[32 + k]) * 0.1f + feat1[o];
        } else {
            int M = w - 4;
            const float4* pr = reinterpret_cast<const float4*>(g_pool2 + ((size_t)atom * 5 + M) * 128);
            const float4* wr = reinterpret_cast<const float4*>(wt2 + k * 132);
#pragma unroll
            for (int j = 0; j < 32; j++) {
                float4 p = pr[j], wv = wr[j];
                acc += p.x * wv.x + p.y * wv.y + p.z * wv.z + p.w * wv.w;
            }
            int o = (atom * 5 + M) * 32 + k;
            out[NA * 32 + NA * 96 + o] = (acc + bsh[64 + k]) * 0.1f + feat2[o];
        }
    }
}

// ---------------------------------------------------------------------------
// Launcher
// ---------------------------------------------------------------------------
extern "C" void kernel_launch(void* const* d_in, const int* in_sizes, int n_in,
                              void* d_out, int out_size) {
    (void)in_sizes; (void)n_in; (void)out_size;
    const float* radial = (const float*)d_in[0];
    const float* sh0    = (const float*)d_in[1];
    const float* sh1    = (const float*)d_in[2];
    const float* sh2    = (const float*)d_in[3];
    const float* feat0  = (const float*)d_in[4];
    const float* feat1  = (const float*)d_in[5];
    const float* feat2  = (const float*)d_in[6];
    const float* W0     = (const float*)d_in[7];
    const float* b0     = (const float*)d_in[8];
    const float* W1     = (const float*)d_in[9];
    const float* b1     = (const float*)d_in[10];
    const float* W2     = (const float*)d_in[11];
    const float* b2     = (const float*)d_in[12];
    const int* centers   = (const int*)d_in[13];
    const int* neighbors = (const int*)d_in[14];
    float* out = (float*)d_out;

    // CSR build over centers
    zero_counts_kernel<<<(NA + 255) / 256, 256>>>();
    hist_kernel<<<(NE + 255) / 256, 256>>>(centers);
    scan_kernel<<<1, 1024>>>();
    scatter_kernel<<<(NE + 255) / 256, 256>>>(centers);

    // per-edge U precompute: warp per edge
    uexp_kernel<<<NE / 8, 256>>>(cgen::h_up, sh0, sh1, sh2);

    // gather: warp per atom
    gather_kernel<<<NA / 8, 256>>>(radial, feat0, feat1, feat2, neighbors);

    atom_kernel<<<1184, 288>>>(feat0, feat1, feat2,
                               W0, b0, W1, b1, W2, b2, out);
}

// round 12
// speedup vs baseline: 1.5412x; 1.5412x over previous
#include <cuda_runtime.h>
#include <cstdint>
#include <cstring>
#include <cmath>

#define NE 200000
#define NA 20000
#define KC 32

// ---------------------------------------------------------------------------
// Device scratch
// ---------------------------------------------------------------------------
__device__ __align__(16) float g_pool0[NA * 96];
__device__ __align__(16) float g_pool1[NA * 3 * 128];
__device__ __align__(16) float g_pool2[NA * 5 * 128];

// CSR over centers
__device__ int g_count[NA];
__device__ int g_off[NA];
__device__ int g_cursor[NA];
__device__ int g_eid[NE];

// CG + metadata passed by value (3020 B < 4KB param limit)
struct UParam { float cg[615]; int md[140]; };

// ---------------------------------------------------------------------------
// Host-side bit-exact replication of np.random.default_rng(42).normal(...)
// ---------------------------------------------------------------------------
namespace cgen {

typedef unsigned __int128 u128;

struct Pcg64 {
    u128 state, inc;
    uint64_t next() {
        const u128 MUL = (((u128)0x2360ed051fc65da4ULL) << 64) | 0x4385df649fccf645ULL;
        state = state * MUL + inc;
        uint64_t hi = (uint64_t)(state >> 64);
        uint64_t lo = (uint64_t)state;
        uint64_t v  = hi ^ lo;
        unsigned rot = (unsigned)(state >> 122);
        return (v >> rot) | (v << ((64u - rot) & 63u));
    }
    double nextd() { return (double)(next() >> 11) * (1.0 / 9007199254740992.0); }
};

static float   h_cg[615];
static UParam  h_up;

struct Init {
    uint64_t zki[256];
    double   zwi[256], zfi[256];
    Pcg64    g;

    double znorm() {
        const double NOR_R = 3.6541528853610088;
        const double NOR_INV_R = 0.27366123732975828;
        for (;;) {
            uint64_t r = g.next();
            int idx = (int)(r & 0xff);
            r >>= 8;
            int sign = (int)(r & 1);
            uint64_t rabs = (r >> 1) & 0x000fffffffffffffULL;
            double x = (double)rabs * zwi[idx];
            if (sign) x = -x;
            if (rabs < zki[idx]) return x;
            if (idx == 0) {
                double xx, yy;
                do {
                    xx = -NOR_INV_R * std::log1p(-g.nextd());
                    yy = -std::log1p(-g.nextd());
                } while (yy + yy <= xx * xx);
                return ((rabs >> 8) & 1) ? -(NOR_R + xx) : NOR_R + xx;
            } else {
                if ((zfi[idx - 1] - zfi[idx]) * g.nextd() + zfi[idx] <
                    std::exp(-0.5 * x * x))
                    return x;
            }
        }
    }

    Init() {
        // ---- SeedSequence(42), pool_size=4 ----
        uint32_t pool[4];
        uint32_t hc = 0x43b0d7e5u;
        auto hashmix = [&hc](uint32_t v) -> uint32_t {
            v ^= hc; hc *= 0x931e8875u; v *= hc; v ^= v >> 16; return v;
        };
        auto mix = [](uint32_t x, uint32_t y) -> uint32_t {
            uint32_t r = x * 0xca01f9ddu - y * 0x4973f715u; r ^= r >> 16; return r;
        };
        pool[0] = hashmix(42u);
        pool[1] = hashmix(0u);
        pool[2] = hashmix(0u);
        pool[3] = hashmix(0u);
        for (int s = 0; s < 4; s++)
            for (int d = 0; d < 4; d++)
                if (s != d) pool[d] = mix(pool[d], hashmix(pool[s]));

        // ---- generate_state(4, uint64) ----
        uint32_t hc2 = 0x8b51f9ddu;
        uint32_t st32[8];
        for (int i = 0; i < 8; i++) {
            uint32_t v = pool[i & 3];
            v ^= hc2; hc2 *= 0x58f38dedu; v *= hc2; v ^= v >> 16;
            st32[i] = v;
        }
        uint64_t s64[4];
        for (int i = 0; i < 4; i++)
            s64[i] = (uint64_t)st32[2 * i] | ((uint64_t)st32[2 * i + 1] << 32);

        // ---- PCG64 seeding ----
        u128 initstate = (((u128)s64[0]) << 64) | s64[1];
        u128 initseq   = (((u128)s64[2]) << 64) | s64[3];
        const u128 MUL = (((u128)0x2360ed051fc65da4ULL) << 64) | 0x4385df649fccf645ULL;
        g.inc = (initseq << 1) | 1;
        g.state = 0;
        g.state = g.state * MUL + g.inc;
        g.state += initstate;
        g.state = g.state * MUL + g.inc;

        // ---- ziggurat tables ----
        const double r = 3.6541528853610088;
        const double M52 = 4503599627370496.0;
        double f_r = std::exp(-0.5 * r * r);
        double V = r * f_r + 1.2533141373155003 * std::erfc(r * 0.7071067811865476);
        double q = V / f_r;
        zki[0] = (uint64_t)((r / q) * M52);
        zki[1] = 0;
        zwi[0] = q / M52; zwi[255] = r / M52;
        zfi[0] = 1.0;     zfi[255] = f_r;
        double dn = r, tn = r;
        for (int i = 254; i >= 1; i--) {
            dn = std::sqrt(-2.0 * std::log(V / dn + std::exp(-0.5 * dn * dn)));
            zki[i + 1] = (uint64_t)((dn / tn) * M52);
            tn = dn;
            zfi[i] = std::exp(-0.5 * dn * dn);
            zwi[i] = dn / M52;
        }

        // ---- draw all 15 CG tensors in dict order ----
        int pos = 0;
        for (int l1 = 0; l1 <= 2; l1++)
            for (int l2 = 0; l2 <= 2; l2++) {
                int lo = l1 > l2 ? l1 - l2 : l2 - l1;
                int hi = (l1 + l2 < 2) ? (l1 + l2) : 2;
                for (int L = lo; L <= hi; L++) {
                    int n = (2 * l1 + 1) * (2 * l2 + 1) * (2 * L + 1);
                    for (int i = 0; i < n; i++)
                        h_cg[pos++] = (float)(znorm() * 0.3);
                }
            }
        std::memcpy(h_up.cg, h_cg, sizeof(h_cg));

        // ---- V metadata table: 11 even-parity paths, padded layout ----
        // md[u] = sh_base | (n_a<<4) | (a_stride<<8) | (cg0<<16)
        struct PathH { int l1, l2, L, base, uoff; };
        const PathH P[11] = {
            {0,0,0,  0,  0},{1,1,0, 44,  4},{2,2,0,390,  8},
            {0,1,1,  1, 16},{1,0,1, 35, 28},{1,2,1,125, 32},{2,1,1,270, 48},
            {0,2,2, 10, 60},{1,1,2, 80, 88},{2,0,2,245,104},{2,2,2,490,112}};
        std::memset(h_up.md, 0, sizeof(h_up.md));
        for (int p = 0; p < 11; p++) {
            int dimL = 2 * P[p].L + 1, dim2 = 2 * P[p].l2 + 1;
            int n_a = 2 * P[p].l1 + 1;
            int ast = dim2 * dimL;
            int shb = (P[p].l1 == 0) ? 0 : (P[p].l1 == 1 ? 1 : 4);
            for (int b = 0; b < dim2; b++)
                for (int M = 0; M < dimL; M++) {
                    int u   = P[p].uoff + b * dimL + M;
                    int cg0 = P[p].base + b * dimL + M;
                    h_up.md[u] = shb | (n_a << 4) | (ast << 8) | (cg0 << 16);
                }
        }
    }
};
static Init g_init;

} // namespace cgen

// ---------------------------------------------------------------------------
// CSR build kernels
// ---------------------------------------------------------------------------
__global__ void zero_counts_kernel() {
    int i = blockIdx.x * blockDim.x + threadIdx.x;
    if (i < NA) g_count[i] = 0;
}

__global__ void hist_kernel(const int* __restrict__ centers) {
    int e = blockIdx.x * blockDim.x + threadIdx.x;
    if (e < NE) atomicAdd(&g_count[centers[e]], 1);
}

__global__ void scan_kernel() {
    __shared__ int s[1024];
    const int t = threadIdx.x;
    const int CH = 20;
    int base = t * CH;
    int loc[CH];
    int sum = 0;
#pragma unroll
    for (int i = 0; i < CH; i++) {
        int idx = base + i;
        int c = (idx < NA) ? g_count[idx] : 0;
        loc[i] = sum;
        sum += c;
    }
    s[t] = sum;
    __syncthreads();
    for (int d = 1; d < 1024; d <<= 1) {
        int v = (t >= d) ? s[t - d] : 0;
        __syncthreads();
        s[t] += v;
        __syncthreads();
    }
    int excl = (t == 0) ? 0 : s[t - 1];
#pragma unroll
    for (int i = 0; i < CH; i++) {
        int idx = base + i;
        if (idx < NA) {
            int o = excl + loc[i];
            g_off[idx] = o;
            g_cursor[idx] = o;
        }
    }
}

__global__ void scatter_kernel(const int* __restrict__ centers) {
    int e = blockIdx.x * blockDim.x + threadIdx.x;
    if (e < NE) {
        int p = atomicAdd(&g_cursor[centers[e]], 1);
        g_eid[p] = e;
    }
}

// ---------------------------------------------------------------------------
// Gather kernel: warp = atom, lane = channel k.
// Per edge: lanes cooperatively compute the 140-slot lane-uniform V table
// (V[b,M] = sum_a sh_l1[e,a]*CG[a,b,M]) into SHARED memory, then contract
// against lane-private feats with ~150 FMAs. No global scratch, no atomics.
// ---------------------------------------------------------------------------
template <int N4>
__device__ __forceinline__ void loadVs(float* d, const float* s) {
    const float4* p = reinterpret_cast<const float4*>(s);
#pragma unroll
    for (int j = 0; j < N4; j++) {
        float4 v = p[j];
        d[4 * j + 0] = v.x; d[4 * j + 1] = v.y;
        d[4 * j + 2] = v.z; d[4 * j + 3] = v.w;
    }
}

__global__ void __launch_bounds__(256) gather_kernel(
    UParam up,
    const float* __restrict__ radial,
    const float* __restrict__ sh0, const float* __restrict__ sh1,
    const float* __restrict__ sh2,
    const float* __restrict__ feat0, const float* __restrict__ feat1,
    const float* __restrict__ feat2,
    const int* __restrict__ neighbors)
{
    __shared__ float scg[616];
    __shared__ float ssh[8][12];
    __shared__ __align__(16) float sV[8][140];

    for (int i = threadIdx.x; i < 615; i += 256) scg[i] = up.cg[i];
    __syncthreads();

    const int k   = threadIdx.x & 31;
    const int wid = threadIdx.x >> 5;
    const int atom = blockIdx.x * 8 + wid;
    if (atom >= NA) return;

    // per-lane V-slot metadata (slots u = k + 32*j, j<5), register-resident
    int mreg[5];
#pragma unroll
    for (int j = 0; j < 5; j++) {
        int u = k + 32 * j;
        mreg[j] = (u < 140) ? up.md[u] : -1;
    }

    float* ssh_w = ssh[wid];
    float* sV_w  = sV[wid];

    const int beg = g_off[atom];
    const int end = beg + g_count[atom];

    float A[3] = {0.f, 0.f, 0.f};
    float B[12], C[20];
#pragma unroll
    for (int i = 0; i < 12; i++) B[i] = 0.f;
#pragma unroll
    for (int i = 0; i < 20; i++) C[i] = 0.f;

    int e = 0, nb = 0;
    float shv = 0.f;
    if (beg < end) {
        e  = __ldg(g_eid + beg);
        nb = __ldg(neighbors + e);
        shv = (k == 0) ? __ldg(sh0 + e)
            : (k < 4)  ? __ldg(sh1 + 3 * e + k - 1)
            : (k < 9)  ? __ldg(sh2 + 5 * e + k - 4) : 0.f;
    }

    for (int it = beg; it < end; it++) {
        // publish this edge's sh to the warp
        if (k < 9) ssh_w[k] = shv;
        __syncwarp();

        // cooperative V compute: each lane fills its <=5 slots
#pragma unroll
        for (int j = 0; j < 5; j++) {
            int m = mreg[j];
            if (m >= 0) {
                int shb = m & 15, na = (m >> 4) & 15;
                int ast = (m >> 8) & 255, cg = m >> 16;
                float acc = 0.f;
#pragma unroll
                for (int a = 0; a < 5; a++)
                    if (a < na) acc = fmaf(ssh_w[shb + a], scg[cg + a * ast], acc);
                sV_w[k + 32 * j] = acc;
            }
        }
        __syncwarp();

        // software-pipeline next edge's index chain + sh load
        int e_n = e, nb_n = nb;
        float shv_n = shv;
        if (it + 1 < end) {
            e_n  = __ldg(g_eid + it + 1);
            nb_n = __ldg(neighbors + e_n);
            shv_n = (k == 0) ? __ldg(sh0 + e_n)
                  : (k < 4)  ? __ldg(sh1 + 3 * e_n + k - 1)
                  : (k < 9)  ? __ldg(sh2 + 5 * e_n + k - 4) : 0.f;
        }

        // lane (channel) loads for current edge
        const float r0 = __ldg(radial + (size_t)e * KC + k);
        const float r1 = __ldg(radial + (size_t)NE * KC + (size_t)e * KC + k);
        const float r2 = __ldg(radial + 2 * (size_t)NE * KC + (size_t)e * KC + k);

        const float f0 = __ldg(feat0 + (size_t)nb * KC + k);
        float f1[3], f2[5];
#pragma unroll
        for (int a = 0; a < 3; a++) f1[a] = __ldg(feat1 + ((size_t)nb * 3 + a) * KC + k);
#pragma unroll
        for (int a = 0; a < 5; a++) f2[a] = __ldg(feat2 + ((size_t)nb * 5 + a) * KC + k);

        // ---- contraction against shared V ----
        // P0 (0,0,0) @0 (1) + P1 (1,1,0) @4 (3)
        {
            float u[8]; loadVs<2>(u, sV_w + 0);
            A[0] = fmaf(r0 * f0, u[0], A[0]);
            A[1] = fmaf(r1, f1[0] * u[4] + f1[1] * u[5] + f1[2] * u[6], A[1]);
        }
        // P2 (2,2,0) @8 (5)
        {
            float u[8]; loadVs<2>(u, sV_w + 8);
            float s = f2[0]*u[0] + f2[1]*u[1] + f2[2]*u[2] + f2[3]*u[3] + f2[4]*u[4];
            A[2] = fmaf(r2, s, A[2]);
        }
        // P3 (0,1,1) @16 (9)
        {
            float u[12]; loadVs<3>(u, sV_w + 16);
#pragma unroll
            for (int M = 0; M < 3; M++) {
                float s = 0.f;
#pragma unroll
                for (int b = 0; b < 3; b++) s = fmaf(f1[b], u[b * 3 + M], s);
                B[M] = fmaf(r0, s, B[M]);
            }
        }
        // P4 (1,0,1) @28 (3)
        {
            float u[4]; loadVs<1>(u, sV_w + 28);
#pragma unroll
            for (int M = 0; M < 3; M++) B[3 + M] = fmaf(r1, f0 * u[M], B[3 + M]);
        }
        // P5 (1,2,1) @32 (15)
        {
            float u[16]; loadVs<4>(u, sV_w + 32);
#pragma unroll
            for (int M = 0; M < 3; M++) {
                float s = 0.f;
#pragma unroll
                for (int b = 0; b < 5; b++) s = fmaf(f2[b], u[b * 3 + M], s);
                B[6 + M] = fmaf(r1, s, B[6 + M]);
            }
        }
        // P6 (2,1,1) @48 (9)
        {
            float u[12]; loadVs<3>(u, sV_w + 48);
#pragma unroll
            for (int M = 0; M < 3; M++) {
                float s = 0.f;
#pragma unroll
                for (int b = 0; b < 3; b++) s = fmaf(f1[b], u[b * 3 + M], s);
                B[9 + M] = fmaf(r2, s, B[9 + M]);
            }
        }
        // P7 (0,2,2) @60 (25)
        {
            float u[28]; loadVs<7>(u, sV_w + 60);
#pragma unroll
            for (int M = 0; M < 5; M++) {
                float s = 0.f;
#pragma unroll
                for (int b = 0; b < 5; b++) s = fmaf(f2[b], u[b * 5 + M], s);
                C[M] = fmaf(r0, s, C[M]);
            }
        }
        // P8 (1,1,2) @88 (15)
        {
            float u[16]; loadVs<4>(u, sV_w + 88);
#pragma unroll
            for (int M = 0; M < 5; M++) {
                float s = 0.f;
#pragma unroll
                for (int b = 0; b < 3; b++) s = fmaf(f1[b], u[b * 5 + M], s);
                C[5 + M] = fmaf(r1, s, C[5 + M]);
            }
        }
        // P9 (2,0,2) @104 (5)
        {
            float u[8]; loadVs<2>(u, sV_w + 104);
#pragma unroll
            for (int M = 0; M < 5; M++) C[10 + M] = fmaf(r2, f0 * u[M], C[10 + M]);
        }
        // P10 (2,2,2) @112 (25)
        {
            float u[28]; loadVs<7>(u, sV_w + 112);
#pragma unroll
            for (int M = 0; M < 5; M++) {
                float s = 0.f;
#pragma unroll
                for (int b = 0; b < 5; b++) s = fmaf(f2[b], u[b * 5 + M], s);
                C[15 + M] = fmaf(r2, s, C[15 + M]);
            }
        }

        e = e_n; nb = nb_n; shv = shv_n;
        __syncwarp();   // protect ssh/sV before next iteration overwrites
    }

    // ---- write pooled rows (coalesced, no atomics) ----
    float* p0 = g_pool0 + (size_t)atom * 96 + k;
    p0[0]  = A[0];
    p0[32] = A[1];
    p0[64] = A[2];

    float* p1 = g_pool1 + (size_t)atom * 384 + k;
#pragma unroll
    for (int M = 0; M < 3; M++) {
        p1[M * 128 + 0]  = B[0 + M];
        p1[M * 128 + 32] = B[3 + M];
        p1[M * 128 + 64] = B[6 + M];
        p1[M * 128 + 96] = B[9 + M];
    }

    float* p2 = g_pool2 + (size_t)atom * 640 + k;
#pragma unroll
    for (int M = 0; M < 5; M++) {
        p2[M * 128 + 0]  = C[0 + M];
        p2[M * 128 + 32] = C[5 + M];
        p2[M * 128 + 64] = C[10 + M];
        p2[M * 128 + 96] = C[15 + M];
    }
}

// ---------------------------------------------------------------------------
// Atom kernel: per-atom linear + bias, *0.1, + residual feat
// ---------------------------------------------------------------------------
__global__ void __launch_bounds__(288) atom_kernel(
    const float* __restrict__ feat0, const float* __restrict__ feat1,
    const float* __restrict__ feat2,
    const float* __restrict__ W0, const float* __restrict__ b0,
    const float* __restrict__ W1, const float* __restrict__ b1,
    const float* __restrict__ W2, const float* __restrict__ b2,
    float* __restrict__ out)
{
    __shared__ __align__(16) float wt0[32 * 100];
    __shared__ __align__(16) float wt1[32 * 132];
    __shared__ __align__(16) float wt2[32 * 132];
    __shared__ float bsh[96];

    for (int i = threadIdx.x; i < 96 * 32; i += 288)
        wt0[(i & 31) * 100 + (i >> 5)] = W0[i];
    for (int i = threadIdx.x; i < 128 * 32; i += 288)
        wt1[(i & 31) * 132 + (i >> 5)] = W1[i];
    for (int i = threadIdx.x; i < 128 * 32; i += 288)
        wt2[(i & 31) * 132 + (i >> 5)] = W2[i];
    if (threadIdx.x < 32) {
        bsh[threadIdx.x]      = b0[threadIdx.x];
        bsh[32 + threadIdx.x] = b1[threadIdx.x];
        bsh[64 + threadIdx.x] = b2[threadIdx.x];
    }
    __syncthreads();

    const int w = threadIdx.x >> 5;
    const int k = threadIdx.x & 31;

    for (int atom = blockIdx.x; atom < NA; atom += gridDim.x) {
        float acc = 0.f;
        if (w == 0) {
            const float4* pr = reinterpret_cast<const float4*>(g_pool0 + (size_t)atom * 96);
            const float4* wr = reinterpret_cast<const float4*>(wt0 + k * 100);
#pragma unroll
            for (int j = 0; j < 24; j++) {
                float4 p = pr[j], wv = wr[j];
                acc += p.x * wv.x + p.y * wv.y + p.z * wv.z + p.w * wv.w;
            }
            int o = atom * 32 + k;
            out[o] = (acc + bsh[k]) * 0.1f + feat0[o];
        } else if (w <= 3) {
            int M = w - 1;
            const float4* pr = reinterpret_cast<const float4*>(g_pool1 + ((size_t)atom * 3 + M) * 128);
            const float4* wr = reinterpret_cast<const float4*>(wt1 + k * 132);
#pragma unroll
            for (int j = 0; j < 32; j++) {
                float4 p = pr[j], wv = wr[j];
                acc += p.x * wv.x + p.y * wv.y + p.z * wv.z + p.w * wv.w;
            }
            int o = (atom * 3 + M) * 32 + k;
            out[NA * 32 + o] = (acc + bsh[32 + k]) * 0.1f + feat1[o];
        } else {
            int M = w - 4;
            const float4* pr = reinterpret_cast<const float4*>(g_pool2 + ((size_t)atom * 5 + M) * 128);
            const float4* wr = reinterpret_cast<const float4*>(wt2 + k * 132);
#pragma unroll
            for (int j = 0; j < 32; j++) {
                float4 p = pr[j], wv = wr[j];
                acc += p.x * wv.x + p.y * wv.y + p.z * wv.z + p.w * wv.w;
            }
            int o = (atom * 5 + M) * 32 + k;
            out[NA * 32 + NA * 96 + o] = (acc + bsh[64 + k]) * 0.1f + feat2[o];
        }
    }
}

// ---------------------------------------------------------------------------
// Launcher
// ---------------------------------------------------------------------------
extern "C" void kernel_launch(void* const* d_in, const int* in_sizes, int n_in,
                              void* d_out, int out_size) {
    (void)in_sizes; (void)n_in; (void)out_size;
    const float* radial = (const float*)d_in[0];
    const float* sh0    = (const float*)d_in[1];
    const float* sh1    = (const float*)d_in[2];
    const float* sh2    = (const float*)d_in[3];
    const float* feat0  = (const float*)d_in[4];
    const float* feat1  = (const float*)d_in[5];
    const float* feat2  = (const float*)d_in[6];
    const float* W0     = (const float*)d_in[7];
    const float* b0     = (const float*)d_in[8];
    const float* W1     = (const float*)d_in[9];
    const float* b1     = (const float*)d_in[10];
    const float* W2     = (const float*)d_in[11];
    const float* b2     = (const float*)d_in[12];
    const int* centers   = (const int*)d_in[13];
    const int* neighbors = (const int*)d_in[14];
    float* out = (float*)d_out;

    // CSR build over centers
    zero_counts_kernel<<<(NA + 255) / 256, 256>>>();
    hist_kernel<<<(NE + 255) / 256, 256>>>(centers);
    scan_kernel<<<1, 1024>>>();
    scatter_kernel<<<(NE + 255) / 256, 256>>>(centers);

    // gather: warp per atom, V computed in shared per edge
    gather_kernel<<<NA / 8, 256>>>(cgen::h_up, radial, sh0, sh1, sh2,
                                   feat0, feat1, feat2, neighbors);

    atom_kernel<<<1184, 288>>>(feat0, feat1, feat2,
                               W0, b0, W1, b1, W2, b2, out);
}

// round 13
// speedup vs baseline: 1.6844x; 1.0929x over previous
#include <cuda_runtime.h>
#include <cstdint>
#include <cstring>
#include <cmath>

#define NE 200000
#define NA 20000
#define KC 32

// ---------------------------------------------------------------------------
// Pooled scratch (concat layout): L0 [NA][1][96], L1 [NA][3][128], L2 [NA][5][128]
// ---------------------------------------------------------------------------
__device__ __align__(16) float g_pool0[NA * 96];
__device__ __align__(16) float g_pool1[NA * 3 * 128];
__device__ __align__(16) float g_pool2[NA * 5 * 128];

// CSR over centers
__device__ int g_count[NA];
__device__ int g_off[NA];
__device__ int g_cursor[NA];
__device__ int g_eid[NE];

// CG constants passed by value (2460 B < 4KB param limit)
struct CgParam { float v[615]; };

// ---------------------------------------------------------------------------
// Host-side bit-exact replication of np.random.default_rng(42).normal(...)
// ---------------------------------------------------------------------------
namespace cgen {

typedef unsigned __int128 u128;

struct Pcg64 {
    u128 state, inc;
    uint64_t next() {
        const u128 MUL = (((u128)0x2360ed051fc65da4ULL) << 64) | 0x4385df649fccf645ULL;
        state = state * MUL + inc;
        uint64_t hi = (uint64_t)(state >> 64);
        uint64_t lo = (uint64_t)state;
        uint64_t v  = hi ^ lo;
        unsigned rot = (unsigned)(state >> 122);
        return (v >> rot) | (v << ((64u - rot) & 63u));
    }
    double nextd() { return (double)(next() >> 11) * (1.0 / 9007199254740992.0); }
};

static float    h_cg[615];
static CgParam  h_cgp;

struct Init {
    uint64_t zki[256];
    double   zwi[256], zfi[256];
    Pcg64    g;

    double znorm() {
        const double NOR_R = 3.6541528853610088;
        const double NOR_INV_R = 0.27366123732975828;
        for (;;) {
            uint64_t r = g.next();
            int idx = (int)(r & 0xff);
            r >>= 8;
            int sign = (int)(r & 1);
            uint64_t rabs = (r >> 1) & 0x000fffffffffffffULL;
            double x = (double)rabs * zwi[idx];
            if (sign) x = -x;
            if (rabs < zki[idx]) return x;
            if (idx == 0) {
                double xx, yy;
                do {
                    xx = -NOR_INV_R * std::log1p(-g.nextd());
                    yy = -std::log1p(-g.nextd());
                } while (yy + yy <= xx * xx);
                return ((rabs >> 8) & 1) ? -(NOR_R + xx) : NOR_R + xx;
            } else {
                if ((zfi[idx - 1] - zfi[idx]) * g.nextd() + zfi[idx] <
                    std::exp(-0.5 * x * x))
                    return x;
            }
        }
    }

    Init() {
        // ---- SeedSequence(42), pool_size=4 ----
        uint32_t pool[4];
        uint32_t hc = 0x43b0d7e5u;
        auto hashmix = [&hc](uint32_t v) -> uint32_t {
            v ^= hc; hc *= 0x931e8875u; v *= hc; v ^= v >> 16; return v;
        };
        auto mix = [](uint32_t x, uint32_t y) -> uint32_t {
            uint32_t r = x * 0xca01f9ddu - y * 0x4973f715u; r ^= r >> 16; return r;
        };
        pool[0] = hashmix(42u);
        pool[1] = hashmix(0u);
        pool[2] = hashmix(0u);
        pool[3] = hashmix(0u);
        for (int s = 0; s < 4; s++)
            for (int d = 0; d < 4; d++)
                if (s != d) pool[d] = mix(pool[d], hashmix(pool[s]));

        // ---- generate_state(4, uint64) ----
        uint32_t hc2 = 0x8b51f9ddu;
        uint32_t st32[8];
        for (int i = 0; i < 8; i++) {
            uint32_t v = pool[i & 3];
            v ^= hc2; hc2 *= 0x58f38dedu; v *= hc2; v ^= v >> 16;
            st32[i] = v;
        }
        uint64_t s64[4];
        for (int i = 0; i < 4; i++)
            s64[i] = (uint64_t)st32[2 * i] | ((uint64_t)st32[2 * i + 1] << 32);

        // ---- PCG64 seeding ----
        u128 initstate = (((u128)s64[0]) << 64) | s64[1];
        u128 initseq   = (((u128)s64[2]) << 64) | s64[3];
        const u128 MUL = (((u128)0x2360ed051fc65da4ULL) << 64) | 0x4385df649fccf645ULL;
        g.inc = (initseq << 1) | 1;
        g.state = 0;
        g.state = g.state * MUL + g.inc;
        g.state += initstate;
        g.state = g.state * MUL + g.inc;

        // ---- ziggurat tables ----
        const double r = 3.6541528853610088;
        const double M52 = 4503599627370496.0;
        double f_r = std::exp(-0.5 * r * r);
        double V = r * f_r + 1.2533141373155003 * std::erfc(r * 0.7071067811865476);
        double q = V / f_r;
        zki[0] = (uint64_t)((r / q) * M52);
        zki[1] = 0;
        zwi[0] = q / M52; zwi[255] = r / M52;
        zfi[0] = 1.0;     zfi[255] = f_r;
        double dn = r, tn = r;
        for (int i = 254; i >= 1; i--) {
            dn = std::sqrt(-2.0 * std::log(V / dn + std::exp(-0.5 * dn * dn)));
            zki[i + 1] = (uint64_t)((dn / tn) * M52);
            tn = dn;
            zfi[i] = std::exp(-0.5 * dn * dn);
            zwi[i] = dn / M52;
        }

        // ---- draw all 15 CG tensors in dict order ----
        int pos = 0;
        for (int l1 = 0; l1 <= 2; l1++)
            for (int l2 = 0; l2 <= 2; l2++) {
                int lo = l1 > l2 ? l1 - l2 : l2 - l1;
                int hi = (l1 + l2 < 2) ? (l1 + l2) : 2;
                for (int L = lo; L <= hi; L++) {
                    int n = (2 * l1 + 1) * (2 * l2 + 1) * (2 * L + 1);
                    for (int i = 0; i < n; i++)
                        h_cg[pos++] = (float)(znorm() * 0.3);
                }
            }
        std::memcpy(h_cgp.v, h_cg, sizeof(h_cg));
    }
};
static Init g_init;

} // namespace cgen

// ---------------------------------------------------------------------------
// CSR build kernels
// ---------------------------------------------------------------------------
__global__ void zero_counts_kernel() {
    int i = blockIdx.x * blockDim.x + threadIdx.x;
    if (i < NA) g_count[i] = 0;
}

__global__ void hist_kernel(const int* __restrict__ centers) {
    int e = blockIdx.x * blockDim.x + threadIdx.x;
    if (e < NE) atomicAdd(&g_count[centers[e]], 1);
}

__global__ void scan_kernel() {
    __shared__ int s[1024];
    const int t = threadIdx.x;
    const int CH = 20;
    int base = t * CH;
    int loc[CH];
    int sum = 0;
#pragma unroll
    for (int i = 0; i < CH; i++) {
        int idx = base + i;
        int c = (idx < NA) ? g_count[idx] : 0;
        loc[i] = sum;
        sum += c;
    }
    s[t] = sum;
    __syncthreads();
    for (int d = 1; d < 1024; d <<= 1) {
        int v = (t >= d) ? s[t - d] : 0;
        __syncthreads();
        s[t] += v;
        __syncthreads();
    }
    int excl = (t == 0) ? 0 : s[t - 1];
#pragma unroll
    for (int i = 0; i < CH; i++) {
        int idx = base + i;
        if (idx < NA) {
            int o = excl + loc[i];
            g_off[idx] = o;
            g_cursor[idx] = o;
        }
    }
}

__global__ void scatter_kernel(const int* __restrict__ centers) {
    int e = blockIdx.x * blockDim.x + threadIdx.x;
    if (e < NE) {
        int p = atomicAdd(&g_cursor[centers[e]], 1);
        g_eid[p] = e;
    }
}

// ---------------------------------------------------------------------------
// Per-edge value bundle (lane-private): 3 radial, 9 feat, 1 sh-lane slot
// ---------------------------------------------------------------------------
struct EVals {
    float shv;              // lane k<9 holds sh value #k for this edge
    float r0, r1, r2;
    float f0, f1[3], f2[5];
};

__device__ __forceinline__ void load_evals(
    EVals& v, int e, int nb, int k,
    const float* __restrict__ radial,
    const float* __restrict__ sh0, const float* __restrict__ sh1,
    const float* __restrict__ sh2,
    const float* __restrict__ feat0, const float* __restrict__ feat1,
    const float* __restrict__ feat2)
{
    v.shv = (k == 0) ? __ldg(sh0 + e)
          : (k < 4)  ? __ldg(sh1 + 3 * e + k - 1)
          : (k < 9)  ? __ldg(sh2 + 5 * e + k - 4) : 0.f;
    v.r0 = __ldg(radial + (size_t)e * KC + k);
    v.r1 = __ldg(radial + (size_t)NE * KC + (size_t)e * KC + k);
    v.r2 = __ldg(radial + 2 * (size_t)NE * KC + (size_t)e * KC + k);
    v.f0 = __ldg(feat0 + (size_t)nb * KC + k);
#pragma unroll
    for (int a = 0; a < 3; a++) v.f1[a] = __ldg(feat1 + ((size_t)nb * 3 + a) * KC + k);
#pragma unroll
    for (int a = 0; a < 5; a++) v.f2[a] = __ldg(feat2 + ((size_t)nb * 5 + a) * KC + k);
}

// ---------------------------------------------------------------------------
// Gather kernel: warp = atom, lane = channel k. Register contraction (R9 math)
// + 2-deep index pipeline + 1-deep value prefetch; sh via shuffle broadcast.
// ---------------------------------------------------------------------------
__global__ void __launch_bounds__(256) gather_kernel(
    CgParam cgp,
    const float* __restrict__ radial,
    const float* __restrict__ sh0, const float* __restrict__ sh1,
    const float* __restrict__ sh2,
    const float* __restrict__ feat0, const float* __restrict__ feat1,
    const float* __restrict__ feat2,
    const int* __restrict__ neighbors)
{
    __shared__ float scg[616];
    for (int i = threadIdx.x; i < 615; i += 256) scg[i] = cgp.v[i];
    __syncthreads();

    const int k = threadIdx.x & 31;
    const int atom = blockIdx.x * 8 + (threadIdx.x >> 5);
    if (atom >= NA) return;

    const int beg = g_off[atom];
    const int end = beg + g_count[atom];

    float A00 = 0.f, A01 = 0.f, A02 = 0.f;
    float B[12], C[20];
#pragma unroll
    for (int i = 0; i < 12; i++) B[i] = 0.f;
#pragma unroll
    for (int i = 0; i < 20; i++) C[i] = 0.f;

    // ---- pipeline prologue ----
    int e1 = 0, nb1 = 0;          // indices for it+1
    EVals cur;
    if (beg < end) {
        int e0  = __ldg(g_eid + beg);
        int nb0 = __ldg(neighbors + e0);
        load_evals(cur, e0, nb0, k, radial, sh0, sh1, sh2, feat0, feat1, feat2);
        if (beg + 1 < end) {
            e1  = __ldg(g_eid + beg + 1);
            nb1 = __ldg(neighbors + e1);
        }
    }

    for (int it = beg; it < end; it++) {
        // ---- issue index chain for it+2 ----
        int e2 = e1, nb2 = nb1;
        if (it + 2 < end) {
            e2  = __ldg(g_eid + it + 2);
            nb2 = __ldg(neighbors + e2);
        }
        // ---- prefetch values for it+1 (indices already resolved) ----
        EVals nxt = cur;
        if (it + 1 < end)
            load_evals(nxt, e1, nb1, k, radial, sh0, sh1, sh2, feat0, feat1, feat2);

        // ---- broadcast sh values from lanes 0..8 ----
        const float s0    = __shfl_sync(0xffffffffu, cur.shv, 0);
        float s1v[3], s2v[5];
#pragma unroll
        for (int a = 0; a < 3; a++) s1v[a] = __shfl_sync(0xffffffffu, cur.shv, 1 + a);
#pragma unroll
        for (int a = 0; a < 5; a++) s2v[a] = __shfl_sync(0xffffffffu, cur.shv, 4 + a);

        const float t10 = s0 * cur.r0;
        float t11[3], t12[5];
#pragma unroll
        for (int a = 0; a < 3; a++) t11[a] = s1v[a] * cur.r1;
#pragma unroll
        for (int a = 0; a < 5; a++) t12[a] = s2v[a] * cur.r2;

        const float f0 = cur.f0;
        float f1[3], f2[5];
#pragma unroll
        for (int a = 0; a < 3; a++) f1[a] = cur.f1[a];
#pragma unroll
        for (int a = 0; a < 5; a++) f2[a] = cur.f2[a];

        // pair products
        float P11[9], P22[25];
#pragma unroll
        for (int a = 0; a < 3; a++)
#pragma unroll
            for (int b = 0; b < 3; b++) P11[a * 3 + b] = t11[a] * f1[b];
#pragma unroll
        for (int a = 0; a < 5; a++)
#pragma unroll
            for (int b = 0; b < 5; b++) P22[a * 5 + b] = t12[a] * f2[b];

        // ---------------- L = 0 ----------------
        A00 = fmaf(scg[0], t10 * f0, A00);
#pragma unroll
        for (int i = 0; i < 9; i++)  A01 = fmaf(P11[i], scg[44 + i],  A01);
#pragma unroll
        for (int i = 0; i < 25; i++) A02 = fmaf(P22[i], scg[390 + i], A02);

        // ---------------- L = 1 ----------------
        {
            float q01[3], q10[3];
#pragma unroll
            for (int b = 0; b < 3; b++) q01[b] = t10 * f1[b];
#pragma unroll
            for (int a = 0; a < 3; a++) q10[a] = t11[a] * f0;
            float q12[15], q21[15];
#pragma unroll
            for (int a = 0; a < 3; a++)
#pragma unroll
                for (int b = 0; b < 5; b++) q12[a * 5 + b] = t11[a] * f2[b];
#pragma unroll
            for (int a = 0; a < 5; a++)
#pragma unroll
                for (int b = 0; b < 3; b++) q21[a * 3 + b] = t12[a] * f1[b];

#pragma unroll
            for (int M = 0; M < 3; M++) {
#pragma unroll
                for (int b = 0; b < 3; b++)  B[0 + M] = fmaf(q01[b], scg[1 + b * 3 + M],   B[0 + M]);
#pragma unroll
                for (int a = 0; a < 3; a++)  B[3 + M] = fmaf(q10[a], scg[35 + a * 3 + M],  B[3 + M]);
#pragma unroll
                for (int i = 0; i < 15; i++) B[6 + M] = fmaf(q12[i], scg[125 + i * 3 + M], B[6 + M]);
#pragma unroll
                for (int i = 0; i < 15; i++) B[9 + M] = fmaf(q21[i], scg[270 + i * 3 + M], B[9 + M]);
            }
        }

        // ---------------- L = 2 ----------------
        {
            float q02[5], q20[5];
#pragma unroll
            for (int b = 0; b < 5; b++) q02[b] = t10 * f2[b];
#pragma unroll
            for (int a = 0; a < 5; a++) q20[a] = t12[a] * f0;

#pragma unroll
            for (int M = 0; M < 5; M++) {
#pragma unroll
                for (int b = 0; b < 5; b++)  C[0 + M]  = fmaf(q02[b], scg[10 + b * 5 + M],  C[0 + M]);
#pragma unroll
                for (int i = 0; i < 9; i++)  C[5 + M]  = fmaf(P11[i], scg[80 + i * 5 + M],  C[5 + M]);
#pragma unroll
                for (int a = 0; a < 5; a++)  C[10 + M] = fmaf(q20[a], scg[245 + a * 5 + M], C[10 + M]);
#pragma unroll
                for (int i = 0; i < 25; i++) C[15 + M] = fmaf(P22[i], scg[490 + i * 5 + M], C[15 + M]);
            }
        }

        // ---- rotate pipeline ----
        cur = nxt;
        e1 = e2; nb1 = nb2;
    }

    // ---- write pooled rows (coalesced, no atomics) ----
    float* p0 = g_pool0 + (size_t)atom * 96 + k;
    p0[0]  = A00;
    p0[32] = A01;
    p0[64] = A02;

    float* p1 = g_pool1 + (size_t)atom * 384 + k;
#pragma unroll
    for (int M = 0; M < 3; M++) {
        p1[M * 128 + 0]  = B[0 + M];
        p1[M * 128 + 32] = B[3 + M];
        p1[M * 128 + 64] = B[6 + M];
        p1[M * 128 + 96] = B[9 + M];
    }

    float* p2 = g_pool2 + (size_t)atom * 640 + k;
#pragma unroll
    for (int M = 0; M < 5; M++) {
        p2[M * 128 + 0]  = C[0 + M];
        p2[M * 128 + 32] = C[5 + M];
        p2[M * 128 + 64] = C[10 + M];
        p2[M * 128 + 96] = C[15 + M];
    }
}

// ---------------------------------------------------------------------------
// Atom kernel: per-atom linear + bias, *0.1, + residual feat
// ---------------------------------------------------------------------------
__global__ void __launch_bounds__(288) atom_kernel(
    const float* __restrict__ feat0, const float* __restrict__ feat1,
    const float* __restrict__ feat2,
    const float* __restrict__ W0, const float* __restrict__ b0,
    const float* __restrict__ W1, const float* __restrict__ b1,
    const float* __restrict__ W2, const float* __restrict__ b2,
    float* __restrict__ out)
{
    __shared__ __align__(16) float wt0[32 * 100];
    __shared__ __align__(16) float wt1[32 * 132];
    __shared__ __align__(16) float wt2[32 * 132];
    __shared__ float bsh[96];

    for (int i = threadIdx.x; i < 96 * 32; i += 288)
        wt0[(i & 31) * 100 + (i >> 5)] = W0[i];
    for (int i = threadIdx.x; i < 128 * 32; i += 288)
        wt1[(i & 31) * 132 + (i >> 5)] = W1[i];
    for (int i = threadIdx.x; i < 128 * 32; i += 288)
        wt2[(i & 31) * 132 + (i >> 5)] = W2[i];
    if (threadIdx.x < 32) {
        bsh[threadIdx.x]      = b0[threadIdx.x];
        bsh[32 + threadIdx.x] = b1[threadIdx.x];
        bsh[64 + threadIdx.x] = b2[threadIdx.x];
    }
    __syncthreads();

    const int w = threadIdx.x >> 5;
    const int k = threadIdx.x & 31;

    for (int atom = blockIdx.x; atom < NA; atom += gridDim.x) {
        float acc = 0.f;
        if (w == 0) {
            const float4* pr = reinterpret_cast<const float4*>(g_pool0 + (size_t)atom * 96);
            const float4* wr = reinterpret_cast<const float4*>(wt0 + k * 100);
#pragma unroll
            for (int j = 0; j < 24; j++) {
                float4 p = pr[j], wv = wr[j];
                acc += p.x * wv.x + p.y * wv.y + p.z * wv.z + p.w * wv.w;
            }
            int o = atom * 32 + k;
            out[o] = (acc + bsh[k]) * 0.1f + feat0[o];
        } else if (w <= 3) {
            int M = w - 1;
            const float4* pr = reinterpret_cast<const float4*>(g_pool1 + ((size_t)atom * 3 + M) * 128);
            const float4* wr = reinterpret_cast<const float4*>(wt1 + k * 132);
#pragma unroll
            for (int j = 0; j < 32; j++) {
                float4 p = pr[j], wv = wr[j];
                acc += p.x * wv.x + p.y * wv.y + p.z * wv.z + p.w * wv.w;
            }
            int o = (atom * 3 + M) * 32 + k;
            out[NA * 32 + o] = (acc + bsh[32 + k]) * 0.1f + feat1[o];
        } else {
            int M = w - 4;
            const float4* pr = reinterpret_cast<const float4*>(g_pool2 + ((size_t)atom * 5 + M) * 128);
            const float4* wr = reinterpret_cast<const float4*>(wt2 + k * 132);
#pragma unroll
            for (int j = 0; j < 32; j++) {
                float4 p = pr[j], wv = wr[j];
                acc += p.x * wv.x + p.y * wv.y + p.z * wv.z + p.w * wv.w;
            }
            int o = (atom * 5 + M) * 32 + k;
            out[NA * 32 + NA * 96 + o] = (acc + bsh[64 + k]) * 0.1f + feat2[o];
        }
    }
}

// ---------------------------------------------------------------------------
// Launcher
// ---------------------------------------------------------------------------
extern "C" void kernel_launch(void* const* d_in, const int* in_sizes, int n_in,
                              void* d_out, int out_size) {
    (void)in_sizes; (void)n_in; (void)out_size;
    const float* radial = (const float*)d_in[0];
    const float* sh0    = (const float*)d_in[1];
    const float* sh1    = (const float*)d_in[2];
    const float* sh2    = (const float*)d_in[3];
    const float* feat0  = (const float*)d_in[4];
    const float* feat1  = (const float*)d_in[5];
    const float* feat2  = (const float*)d_in[6];
    const float* W0     = (const float*)d_in[7];
    const float* b0     = (const float*)d_in[8];
    const float* W1     = (const float*)d_in[9];
    const float* b1     = (const float*)d_in[10];
    const float* W2     = (const float*)d_in[11];
    const float* b2     = (const float*)d_in[12];
    const int* centers   = (const int*)d_in[13];
    const int* neighbors = (const int*)d_in[14];
    float* out = (float*)d_out;

    // CSR build over centers
    zero_counts_kernel<<<(NA + 255) / 256, 256>>>();
    hist_kernel<<<(NE + 255) / 256, 256>>>(centers);
    scan_kernel<<<1, 1024>>>();
    scatter_kernel<<<(NE + 255) / 256, 256>>>(centers);

    // gather: warp per atom, deep value prefetch
    gather_kernel<<<NA / 8, 256>>>(cgen::h_cgp, radial, sh0, sh1, sh2,
                                   feat0, feat1, feat2, neighbors);

    atom_kernel<<<1184, 288>>>(feat0, feat1, feat2,
                               W0, b0, W1, b1, W2, b2, out);
}